// round 2
// baseline (speedup 1.0000x reference)
#include <cuda_runtime.h>
#include <cooperative_groups.h>
#include <float.h>

namespace cg = cooperative_groups;

// Problem constants
#define B_   4
#define C_   64
#define T_   32
#define WH_  4096                 // W*H per frame
#define PLANE4_ ((T_ * WH_) / 4)  // float4 per (b,c) plane: 32768
#define FRAME4_ (WH_ / 4)         // float4 per frame: 1024

#define CHUNK_   512              // spatial positions per block
#define CHUNK4_  (CHUNK_ / 4)     // 128 float4
#define NCHUNK_  (WH_ / CHUNK_)   // 8 blocks per frame == cluster size
#define NTHREADS 512

// Dynamic SMEM layout (floats):
//   tile   [0, 32768)            : 64 channels x 512 positions (x data, retained)
//   attn_s [32768, 33280)        : 512 (exp values, then normalized attn)
//   red    [33280, 33296)        : 16  (warp partials)
//   part   [33312]               : this block's exp-sum (16B-aligned slot for DSMEM)
#define TILE_OFF   0
#define ATTN_OFF   32768
#define RED_OFF    33280
#define PART_OFF   33312
#define SMEM_FLOATS 33328
#define SMEM_BYTES  (SMEM_FLOATS * 4)

__device__ __forceinline__ float sigmoidf_(float v) {
    return 1.0f / (1.0f + __expf(-v));
}

extern __shared__ float smem[];

__global__ __launch_bounds__(NTHREADS) __cluster_dims__(NCHUNK_, 1, 1)
void fused_mixattn_kernel(const float* __restrict__ x,
                          const float* __restrict__ skin,
                          float* __restrict__ out,
                          float* __restrict__ attn)
{
    const int chunk = blockIdx.x;       // 0..7  == cluster rank
    const int bt    = blockIdx.y;       // 0..127
    const int b     = bt >> 5;          // / T_
    const int t     = bt & 31;          // % T_
    const int tid   = threadIdx.x;      // 0..511

    // float4 base of this block's chunk within channel 0
    const size_t base4 = ((size_t)(b * C_ * T_) + t) * FRAME4_ + (size_t)chunk * CHUNK4_;
    const float4* __restrict__ x4   = (const float4*)x;
    float4* __restrict__ out4       = (float4*)out;
    float4* __restrict__ tile4      = (float4*)(smem + TILE_OFF);

    // ---- Phase 1: stream x chunk (64 c x 512 pos = 128KB) into SMEM ----
    // idx = c*128 + p4 ; scalar layout: smem[c*512 + pos]
    #pragma unroll
    for (int i = 0; i < 16; i++) {
        const int idx = i * NTHREADS + tid;
        const int c   = idx >> 7;          // / 128
        const int p4  = idx & 127;
        tile4[idx] = x4[base4 + (size_t)c * PLANE4_ + p4];
    }
    __syncthreads();

    // ---- Phase 2: per-position channel sum/max from SMEM ----
    float s = 0.0f, m = -FLT_MAX;
    #pragma unroll 8
    for (int c = 0; c < C_; c++) {
        const float v = smem[TILE_OFF + c * CHUNK_ + tid];
        s += v;
        m = fmaxf(m, v);
    }

    const float sk = skin[(size_t)bt * WH_ + chunk * CHUNK_ + tid];
    const float f  = sigmoidf_(s * (1.0f / C_)) + sigmoidf_(m) + sk;   // in (0,3)
    const float e  = __expf(f);                                        // stable, no max needed
    smem[ATTN_OFF + tid] = e;

    // ---- block reduction: sum of e over 512 threads ----
    float ls = e;
    #pragma unroll
    for (int o = 16; o; o >>= 1) ls += __shfl_xor_sync(0xffffffffu, ls, o);
    if ((tid & 31) == 0) smem[RED_OFF + (tid >> 5)] = ls;
    __syncthreads();
    if (tid == 0) {
        float v = 0.0f;
        #pragma unroll
        for (int w = 0; w < 16; w++) v += smem[RED_OFF + w];
        smem[PART_OFF] = v;
    }

    // ---- cluster reduction: combine the 8 chunk partials via DSMEM ----
    cg::cluster_group cluster = cg::this_cluster();
    cluster.sync();
    if (tid < NCHUNK_) {
        const float* rp = cluster.map_shared_rank(smem + PART_OFF, tid);
        smem[RED_OFF + tid] = *rp;
    }
    __syncthreads();
    float tot = 0.0f;
    #pragma unroll
    for (int r = 0; r < NCHUNK_; r++) tot += smem[RED_OFF + r];
    const float inv_sum = __frcp_rn(tot);

    // ---- normalize, write attn ----
    const float a = smem[ATTN_OFF + tid] * inv_sum;
    attn[(size_t)bt * WH_ + chunk * CHUNK_ + tid] = a;
    __syncthreads();              // everyone done reading e before overwrite
    smem[ATTN_OFF + tid] = a;
    __syncthreads();

    // ---- Phase 3: out = tile * attn, streamed from SMEM ----
    const float4* __restrict__ attn4 = (const float4*)(smem + ATTN_OFF);
    #pragma unroll
    for (int i = 0; i < 16; i++) {
        const int idx = i * NTHREADS + tid;
        const int c   = idx >> 7;
        const int p4  = idx & 127;
        const float4 xv = tile4[idx];
        const float4 av = attn4[p4];
        float4 ov;
        ov.x = xv.x * av.x; ov.y = xv.y * av.y;
        ov.z = xv.z * av.z; ov.w = xv.w * av.w;
        out4[base4 + (size_t)c * PLANE4_ + p4] = ov;
    }

    // No trailing cluster.sync needed: the only DSMEM traffic (partial reads)
    // is already globally ordered before every block's phase 3; blocks only
    // read their own SMEM afterwards. cluster teardown handles residency.
    cluster.sync();
}

extern "C" void kernel_launch(void* const* d_in, const int* in_sizes, int n_in,
                              void* d_out, int out_size)
{
    const float* x    = (const float*)d_in[0];
    const float* skin = (const float*)d_in[1];
    float* out  = (float*)d_out;
    float* attn = out + (size_t)B_ * C_ * T_ * WH_;   // second output region

    static bool attr_set = false;
    if (!attr_set) {
        cudaFuncSetAttribute(fused_mixattn_kernel,
                             cudaFuncAttributeMaxDynamicSharedMemorySize, SMEM_BYTES);
        attr_set = true;
    }

    dim3 grid(NCHUNK_, B_ * T_);   // (8, 128) -> 1024 blocks, clusters of 8 along x
    fused_mixattn_kernel<<<grid, NTHREADS, SMEM_BYTES>>>(x, skin, out, attn);
}

// round 3
// speedup vs baseline: 1.3635x; 1.3635x over previous
#include <cuda_runtime.h>
#include <float.h>

// Problem constants
#define B_   4
#define C_   64
#define T_   32
#define WH_  4096                  // W*H per frame
#define FRAME4_ (WH_ / 4)          // 1024 float4 per frame
#define PLANE4_ ((T_ * WH_) / 4)   // 32768 float4 per (b,c) plane
#define NBT_ (B_ * T_)             // 128 frames

#define K1_CHUNKS  4               // blocks per frame in pass 1
#define K1_THREADS 256             // threads per block (1 float4 each)

// Scratch (device globals — no allocation)
__device__ float g_e[(size_t)NBT_ * WH_];          // unnormalized exp(fusion), 2MB
__device__ float g_part[NBT_ * K1_CHUNKS];         // per-chunk exp-sums

__device__ __forceinline__ float sigmoidf_(float v) {
    return 1.0f / (1.0f + __expf(-v));
}

// ---------------- Pass 1: channel reduce + exp, partial sums ----------------
// grid (K1_CHUNKS, NBT_), 256 threads. Each thread owns one float4 (4 positions)
// and loops over the 64 channels.
__global__ __launch_bounds__(K1_THREADS) void reduce_exp_kernel(
    const float* __restrict__ x,
    const float* __restrict__ skin)
{
    const int chunk = blockIdx.x;              // 0..3
    const int bt    = blockIdx.y;              // 0..127
    const int b     = bt >> 5;
    const int t     = bt & 31;
    const int tid   = threadIdx.x;
    const int p4    = chunk * K1_THREADS + tid;      // 0..1023 within frame

    const size_t base4 = ((size_t)(b * C_ * T_) + t) * FRAME4_ + p4;
    const float4* __restrict__ x4 = (const float4*)x;

    float4 s = make_float4(0.f, 0.f, 0.f, 0.f);
    float4 m = make_float4(-FLT_MAX, -FLT_MAX, -FLT_MAX, -FLT_MAX);

    #pragma unroll 8
    for (int c = 0; c < C_; c++) {
        const float4 v = x4[base4 + (size_t)c * PLANE4_];
        s.x += v.x; s.y += v.y; s.z += v.z; s.w += v.w;
        m.x = fmaxf(m.x, v.x); m.y = fmaxf(m.y, v.y);
        m.z = fmaxf(m.z, v.z); m.w = fmaxf(m.w, v.w);
    }

    const float4 k = ((const float4*)skin)[(size_t)bt * FRAME4_ + p4];

    const float inv_c = 1.0f / (float)C_;
    float4 e;
    // fusion in (0,3): exp is safe without max subtraction
    e.x = __expf(sigmoidf_(s.x * inv_c) + sigmoidf_(m.x) + k.x);
    e.y = __expf(sigmoidf_(s.y * inv_c) + sigmoidf_(m.y) + k.y);
    e.z = __expf(sigmoidf_(s.z * inv_c) + sigmoidf_(m.z) + k.z);
    e.w = __expf(sigmoidf_(s.w * inv_c) + sigmoidf_(m.w) + k.w);

    ((float4*)g_e)[(size_t)bt * FRAME4_ + p4] = e;

    // block sum of e
    float ls = e.x + e.y + e.z + e.w;
    #pragma unroll
    for (int o = 16; o; o >>= 1) ls += __shfl_xor_sync(0xffffffffu, ls, o);

    __shared__ float red[8];
    if ((tid & 31) == 0) red[tid >> 5] = ls;
    __syncthreads();
    if (tid == 0) {
        float v = red[0];
        #pragma unroll
        for (int w = 1; w < 8; w++) v += red[w];
        g_part[bt * K1_CHUNKS + chunk] = v;
    }
}

// ---------------- Pass 2: out = x * e * inv_sum; c==0 writes attn ----------------
// grid (128, 256) blocks of 256 threads; each thread one float4.
// A block covers 256 contiguous float4 -> single frame t = blockIdx.x >> 2.
__global__ __launch_bounds__(256) void apply_kernel(
    const float* __restrict__ x,
    float* __restrict__ out,
    float* __restrict__ attn)
{
    const int plane = blockIdx.y;              // b*C + c, 0..255
    const int b     = plane >> 6;
    const int c     = plane & 63;
    const int i4    = blockIdx.x * 256 + threadIdx.x;   // 0..32767 within plane
    const int t     = blockIdx.x >> 2;                   // frame (constant per block)
    const int bt    = b * T_ + t;

    __shared__ float inv;
    if (threadIdx.x == 0) {
        const float* p = &g_part[bt * K1_CHUNKS];
        inv = __frcp_rn(p[0] + p[1] + p[2] + p[3]);
    }
    __syncthreads();

    const size_t px = (size_t)plane * PLANE4_ + i4;
    const size_t pa = (size_t)b * PLANE4_ + i4;   // index into g_e / attn (B*T*WH)

    const float4 xv = ((const float4*)x)[px];
    const float4 ev = ((const float4*)g_e)[pa];

    float4 a;
    a.x = ev.x * inv; a.y = ev.y * inv; a.z = ev.z * inv; a.w = ev.w * inv;

    float4 ov;
    ov.x = xv.x * a.x; ov.y = xv.y * a.y;
    ov.z = xv.z * a.z; ov.w = xv.w * a.w;
    ((float4*)out)[px] = ov;

    if (c == 0) ((float4*)attn)[pa] = a;
}

extern "C" void kernel_launch(void* const* d_in, const int* in_sizes, int n_in,
                              void* d_out, int out_size)
{
    const float* x    = (const float*)d_in[0];
    const float* skin = (const float*)d_in[1];
    float* out  = (float*)d_out;
    float* attn = out + (size_t)B_ * C_ * T_ * WH_;   // second output region

    dim3 g1(K1_CHUNKS, NBT_);
    reduce_exp_kernel<<<g1, K1_THREADS>>>(x, skin);

    dim3 g2(PLANE4_ / 256, B_ * C_);
    apply_kernel<<<g2, 256>>>(x, out, attn);
}

// round 4
// speedup vs baseline: 1.4627x; 1.0728x over previous
#include <cuda_runtime.h>
#include <float.h>

// Problem constants
#define B_   4
#define C_   64
#define T_   32
#define WH_  4096                  // W*H per frame
#define FRAME4_ (WH_ / 4)          // 1024 float4 per frame
#define PLANE4_ ((T_ * WH_) / 4)   // 32768 float4 per (b,c) plane
#define NBT_ (B_ * T_)             // 128 frames

#define K1_CHUNKS  8               // blocks per frame in pass 1
#define K1_THREADS 128             // threads per block (1 float4 each)

// Scratch (device globals — no allocation)
__device__ float g_e[(size_t)NBT_ * WH_];          // unnormalized exp(fusion), 2MB
__device__ float g_part[NBT_ * K1_CHUNKS];         // per-chunk exp-sums

__device__ __forceinline__ float sigmoidf_(float v) {
    return 1.0f / (1.0f + __expf(-v));
}

// ---------------- Pass 1: channel reduce + exp, partial sums ----------------
// grid (K1_CHUNKS, NBT_) = (8,128) -> 1024 blocks, 128 threads, 1 float4/thread.
__global__ __launch_bounds__(K1_THREADS) void reduce_exp_kernel(
    const float* __restrict__ x,
    const float* __restrict__ skin)
{
    const int chunk = blockIdx.x;              // 0..7
    const int bt    = blockIdx.y;              // 0..127
    const int b     = bt >> 5;
    const int t     = bt & 31;
    const int tid   = threadIdx.x;             // 0..127
    const int p4    = chunk * K1_THREADS + tid;      // 0..1023 within frame

    const size_t base4 = ((size_t)(b * C_ * T_) + t) * FRAME4_ + p4;
    const float4* __restrict__ x4 = (const float4*)x;

    float4 s = make_float4(0.f, 0.f, 0.f, 0.f);
    float4 m = make_float4(-FLT_MAX, -FLT_MAX, -FLT_MAX, -FLT_MAX);

    #pragma unroll 8
    for (int c = 0; c < C_; c++) {
        const float4 v = x4[base4 + (size_t)c * PLANE4_];
        s.x += v.x; s.y += v.y; s.z += v.z; s.w += v.w;
        m.x = fmaxf(m.x, v.x); m.y = fmaxf(m.y, v.y);
        m.z = fmaxf(m.z, v.z); m.w = fmaxf(m.w, v.w);
    }

    const float4 k = ((const float4*)skin)[(size_t)bt * FRAME4_ + p4];

    const float inv_c = 1.0f / (float)C_;
    float4 e;
    // fusion in (0,3): exp is safe without max subtraction
    e.x = __expf(sigmoidf_(s.x * inv_c) + sigmoidf_(m.x) + k.x);
    e.y = __expf(sigmoidf_(s.y * inv_c) + sigmoidf_(m.y) + k.y);
    e.z = __expf(sigmoidf_(s.z * inv_c) + sigmoidf_(m.z) + k.z);
    e.w = __expf(sigmoidf_(s.w * inv_c) + sigmoidf_(m.w) + k.w);

    ((float4*)g_e)[(size_t)bt * FRAME4_ + p4] = e;

    // block sum of e (128 threads = 4 warps)
    float ls = e.x + e.y + e.z + e.w;
    #pragma unroll
    for (int o = 16; o; o >>= 1) ls += __shfl_xor_sync(0xffffffffu, ls, o);

    __shared__ float red[4];
    if ((tid & 31) == 0) red[tid >> 5] = ls;
    __syncthreads();
    if (tid == 0)
        g_part[bt * K1_CHUNKS + chunk] = red[0] + red[1] + red[2] + red[3];
}

// ---------------- Pass 2: out = x * e * inv_sum; c==0 planes write attn ----------------
// grid (64, 256): blockIdx.x covers 512 float4 of a plane (2 per thread).
// Frame t = blockIdx.x >> 1 is block-constant. No barrier: every thread
// computes inv from 4 L1-broadcast scalar loads.
__global__ __launch_bounds__(256) void apply_kernel(
    const float* __restrict__ x,
    float* __restrict__ out,
    float* __restrict__ attn)
{
    const int plane = blockIdx.y;              // b*C + c, 0..255
    const int b     = plane >> 6;
    const int c     = plane & 63;
    const int i4    = blockIdx.x * 512 + threadIdx.x;   // first float4 index
    const int t     = blockIdx.x >> 1;                   // block-constant frame
    const int bt    = b * T_ + t;

    const size_t px = (size_t)plane * PLANE4_ + i4;
    const size_t pa = (size_t)b * PLANE4_ + i4;   // index into g_e / attn

    const float4 xv0 = ((const float4*)x)[px];
    const float4 xv1 = ((const float4*)x)[px + 256];
    const float4 ev0 = ((const float4*)g_e)[pa];
    const float4 ev1 = ((const float4*)g_e)[pa + 256];

    const float* __restrict__ p = &g_part[bt * K1_CHUNKS];
    float tot = 0.f;
    #pragma unroll
    for (int r = 0; r < K1_CHUNKS; r++) tot += p[r];
    const float inv = __frcp_rn(tot);

    float4 a0, a1;
    a0.x = ev0.x * inv; a0.y = ev0.y * inv; a0.z = ev0.z * inv; a0.w = ev0.w * inv;
    a1.x = ev1.x * inv; a1.y = ev1.y * inv; a1.z = ev1.z * inv; a1.w = ev1.w * inv;

    float4 o0, o1;
    o0.x = xv0.x * a0.x; o0.y = xv0.y * a0.y; o0.z = xv0.z * a0.z; o0.w = xv0.w * a0.w;
    o1.x = xv1.x * a1.x; o1.y = xv1.y * a1.y; o1.z = xv1.z * a1.z; o1.w = xv1.w * a1.w;

    ((float4*)out)[px]       = o0;
    ((float4*)out)[px + 256] = o1;

    if (c == 0) {
        ((float4*)attn)[pa]       = a0;
        ((float4*)attn)[pa + 256] = a1;
    }
}

extern "C" void kernel_launch(void* const* d_in, const int* in_sizes, int n_in,
                              void* d_out, int out_size)
{
    const float* x    = (const float*)d_in[0];
    const float* skin = (const float*)d_in[1];
    float* out  = (float*)d_out;
    float* attn = out + (size_t)B_ * C_ * T_ * WH_;   // second output region

    dim3 g1(K1_CHUNKS, NBT_);
    reduce_exp_kernel<<<g1, K1_THREADS>>>(x, skin);

    dim3 g2(PLANE4_ / 512, B_ * C_);
    apply_kernel<<<g2, 256>>>(x, out, attn);
}